// round 1
// baseline (speedup 1.0000x reference)
#include <cuda_runtime.h>

// Problem constants
#define B_    32
#define H_    64
#define W_    64
#define CIN   384
#define CHID  128

// Tiling
#define TM    64    // pixels per CTA (one full image row)
#define TN    128   // all hidden channels
#define TK    32    // K-chunk (cin slice per tap)
#define APAD  68    // padded row stride for transposed A tile (272B, 16B-aligned)

__global__ __launch_bounds__(256, 3)
void keypoint_conv_kernel(const float* __restrict__ x,
                          const float* __restrict__ w1,
                          const float* __restrict__ b1,
                          const float* __restrict__ w2,
                          const float* __restrict__ b2,
                          float* __restrict__ out)
{
    // Shared memory: A/B tiles during mainloop, reused as H (hidden) in epilogue.
    // Hs needs 64*129 = 8256 floats; As (32*68=2176) + Bs (32*128=4096) = 6272 fits inside.
    __shared__ __align__(16) float smem[TM * (TN + 1)];
    __shared__ float w2s[CHID];

    float (*As)[APAD] = reinterpret_cast<float (*)[APAD]>(smem);            // [TK][APAD]
    float (*Bs)[TN]   = reinterpret_cast<float (*)[TN]>(smem + TK * APAD);  // [TK][TN]
    float (*Hs)[TN+1] = reinterpret_cast<float (*)[TN+1]>(smem);            // [TM][TN+1]

    const int tid = threadIdx.x;
    const int bh  = blockIdx.x;          // 0..B*H-1
    const int b   = bh >> 6;
    const int h   = bh & 63;

    if (tid < CHID) w2s[tid] = w2[tid];

    // Thread -> register tile mapping: 8 (tm) x 32 (tn) threads, each 8x4 outputs.
    const int tm    = tid >> 5;          // 0..7  (constant within a warp -> A broadcast)
    const int tn    = tid & 31;          // 0..31
    const int mBase = tm * 8;
    const int nBase = tn * 4;

    float acc[8][4];
    #pragma unroll
    for (int i = 0; i < 8; i++)
        #pragma unroll
        for (int j = 0; j < 4; j++)
            acc[i][j] = 0.f;

    float bias[4];
    #pragma unroll
    for (int j = 0; j < 4; j++) bias[j] = b1[nBase + j];

    const float* ximg = x + (size_t)b * H_ * W_ * CIN;

    for (int tap = 0; tap < 9; tap++) {
        const int dy  = tap / 3 - 1;
        const int dx  = tap % 3 - 1;
        const int hin = h + dy;
        if (hin < 0 || hin >= H_) continue;   // whole tap contributes zero -> skip

        const float* xr   = ximg + (size_t)hin * W_ * CIN;
        const float* wtap = w1 + (size_t)tap * CIN * CHID;

        for (int c0 = 0; c0 < CIN; c0 += TK) {
            // ---- Load A transposed: As[k][p] = x[b, hin, p+dx, c0+k] (0 outside) ----
            // 64 pixels * 32 k = 2048 floats = 512 float4 global loads
            #pragma unroll
            for (int f = tid; f < 512; f += 256) {
                const int p   = f >> 3;   // pixel 0..63
                const int c4  = f & 7;    // which float4 of the 32-k slice
                const int win = p + dx;
                float4 v = make_float4(0.f, 0.f, 0.f, 0.f);
                if ((unsigned)win < (unsigned)W_)
                    v = *reinterpret_cast<const float4*>(xr + (size_t)win * CIN + c0 + c4 * 4);
                As[c4 * 4 + 0][p] = v.x;
                As[c4 * 4 + 1][p] = v.y;
                As[c4 * 4 + 2][p] = v.z;
                As[c4 * 4 + 3][p] = v.w;
            }
            // ---- Load B: Bs[k][n] = w1[tap, c0+k, n] ----
            #pragma unroll
            for (int f = tid; f < 1024; f += 256) {
                const int k  = f >> 5;
                const int n4 = f & 31;
                *reinterpret_cast<float4*>(&Bs[k][n4 * 4]) =
                    *reinterpret_cast<const float4*>(wtap + (size_t)(c0 + k) * CHID + n4 * 4);
            }
            __syncthreads();

            // ---- Compute: 32 k-steps, 8x4 outer product each ----
            #pragma unroll
            for (int k = 0; k < TK; k++) {
                const float4 a0 = *reinterpret_cast<const float4*>(&As[k][mBase]);
                const float4 a1 = *reinterpret_cast<const float4*>(&As[k][mBase + 4]);
                const float4 bv = *reinterpret_cast<const float4*>(&Bs[k][nBase]);
                const float av[8] = {a0.x, a0.y, a0.z, a0.w, a1.x, a1.y, a1.z, a1.w};
                #pragma unroll
                for (int i = 0; i < 8; i++) {
                    acc[i][0] += av[i] * bv.x;
                    acc[i][1] += av[i] * bv.y;
                    acc[i][2] += av[i] * bv.z;
                    acc[i][3] += av[i] * bv.w;
                }
            }
            __syncthreads();
        }
    }

    // ---- Epilogue: bias + ReLU into Hs (reuses A/B smem; last sync already done) ----
    #pragma unroll
    for (int i = 0; i < 8; i++)
        #pragma unroll
        for (int j = 0; j < 4; j++)
            Hs[mBase + i][nBase + j] = fmaxf(acc[i][j] + bias[j], 0.f);
    __syncthreads();

    // ---- conv1x1 + sigmoid: 64 threads, one pixel each ----
    if (tid < TM) {
        float s = 0.f;
        #pragma unroll
        for (int n = 0; n < CHID; n++)
            s += Hs[tid][n] * w2s[n];
        s += b2[0];
        out[(size_t)bh * W_ + tid] = 1.f / (1.f + __expf(-s));
    }
}

extern "C" void kernel_launch(void* const* d_in, const int* in_sizes, int n_in,
                              void* d_out, int out_size)
{
    const float* x  = (const float*)d_in[0];   // (32,64,64,384)
    const float* w1 = (const float*)d_in[1];   // (3,3,384,128) HWIO
    const float* b1 = (const float*)d_in[2];   // (128)
    const float* w2 = (const float*)d_in[3];   // (1,1,128,1) -> (128)
    const float* b2 = (const float*)d_in[4];   // (1)
    float* out = (float*)d_out;                // (32,64,64,1)

    keypoint_conv_kernel<<<B_ * H_, 256>>>(x, w1, b1, w2, b2, out);
}

// round 3
// speedup vs baseline: 3.9857x; 3.9857x over previous
#include <cuda_runtime.h>
#include <cuda_bf16.h>
#include <cstdint>

#define B_    32
#define H_    64
#define W_    64
#define CIN   384
#define CHID  128
#define NCC   6          // 384 / 64 channel chunks
#define NTAPS 9
#define NCHUNK (NCC * NTAPS)   // 54
#define THREADS 256

// ---- dynamic smem layout (bytes) ----
#define OFF_B1S 0
#define OFF_W2S 512
#define OFF_A0  1024
#define OFF_A1  (OFF_A0 + 32768)
#define OFF_B0  (OFF_A1 + 32768)
#define OFF_B1  (OFF_B0 + 16384)
#define SMEM_TOTAL (OFF_B1 + 16384)   // 99328

// W1 in bf16, fragment order: [tap][cc][half][ks][j][lane] x 16B
__device__ __align__(16) uint4 g_w1b[NTAPS * NCC * 2 * 4 * 4 * 32];  // 55296 uint4

__device__ __forceinline__ uint32_t smem_u32(const void* p) {
    uint32_t a;
    asm("{ .reg .u64 t; cvta.to.shared.u64 t, %1; cvt.u32.u64 %0, t; }" : "=r"(a) : "l"(p));
    return a;
}
__device__ __forceinline__ uint32_t cvt2(float lo, float hi) {
    __nv_bfloat162 h = __float22bfloat162_rn(make_float2(lo, hi));
    return *reinterpret_cast<uint32_t*>(&h);
}
__device__ __forceinline__ void sts128(uint32_t a, uint32_t x, uint32_t y, uint32_t z, uint32_t w) {
    asm volatile("st.shared.v4.b32 [%0], {%1,%2,%3,%4};" :: "r"(a), "r"(x), "r"(y), "r"(z), "r"(w) : "memory");
}
__device__ __forceinline__ void lds128(uint32_t* r, uint32_t a) {
    asm volatile("ld.shared.v4.b32 {%0,%1,%2,%3}, [%4];"
                 : "=r"(r[0]), "=r"(r[1]), "=r"(r[2]), "=r"(r[3]) : "r"(a));
}
__device__ __forceinline__ void mma_bf16(float* d, const uint32_t* a, uint32_t b0, uint32_t b1) {
    asm volatile("mma.sync.aligned.m16n8k16.row.col.f32.bf16.bf16.f32 "
                 "{%0,%1,%2,%3}, {%4,%5,%6,%7}, {%8,%9}, {%0,%1,%2,%3};"
                 : "+f"(d[0]), "+f"(d[1]), "+f"(d[2]), "+f"(d[3])
                 : "r"(a[0]), "r"(a[1]), "r"(a[2]), "r"(a[3]), "r"(b0), "r"(b1));
}

// ---- prep: W1 (HWIO fp32) -> g_w1b (bf16, mma-fragment order) ----
__global__ void prep_w1_kernel(const float* __restrict__ w1) {
    int u = blockIdx.x * 256 + threadIdx.x;          // 0..55295
    int lane = u & 31;  int r = u >> 5;
    int j    = r & 3;   r >>= 2;
    int ks   = r & 3;   r >>= 2;
    int half = r & 1;   r >>= 1;
    int cc   = r % NCC;
    int tap  = r / NCC;
    int g = lane >> 2, t = lane & 3;
    uint32_t wd[4];
    #pragma unroll
    for (int w = 0; w < 4; w++) {                    // word: [nt-pair][k-low/high]
        int nt = 2 * j + (w >> 1);
        int n  = half * 64 + nt * 8 + g;
        int kb = cc * 64 + ks * 16 + 2 * t + (w & 1) * 8;
        float f0 = w1[(size_t)(tap * CIN + kb) * CHID + n];
        float f1 = w1[(size_t)(tap * CIN + kb + 1) * CHID + n];
        wd[w] = cvt2(f0, f1);
    }
    g_w1b[u] = make_uint4(wd[0], wd[1], wd[2], wd[3]);
}

// ---- A staging: convert 256px x 64ch fp32 -> bf16 fragments in smem ----
__device__ __forceinline__ void stageA(const float* __restrict__ x, uint32_t abase,
                                       int b, int rq, int tap, int cc, int wid, int lane) {
    const int dy = tap / 3 - 1, dx = tap % 3 - 1;
    const int g = lane >> 2, t = lane & 3;
    #pragma unroll
    for (int hf = 0; hf < 2; hf++) {
        float2 v[4][4];
        #pragma unroll
        for (int pp = 0; pp < 4; pp++) {
            const int p  = wid * 8 + hf * 4 + pp;    // plane 0..63
            const int mt = p >> 2, ks = p & 3;
            const int hin = rq * 4 + (mt >> 2) + dy;
            const int wl  = (mt & 3) * 16 + g + dx;
            const int wh  = wl + 8;
            const int k   = cc * 64 + ks * 16 + 2 * t;
            const bool vh_ = (unsigned)hin < 64u;
            const bool vlo = vh_ && ((unsigned)wl < 64u);
            const bool vhi = vh_ && ((unsigned)wh < 64u);
            const float* rowp = x + ((size_t)(b * 64 + hin) * 64) * CIN;
            const float2 z = make_float2(0.f, 0.f);
            v[pp][0] = vlo ? *(const float2*)(rowp + (size_t)wl * CIN + k)     : z;
            v[pp][1] = vhi ? *(const float2*)(rowp + (size_t)wh * CIN + k)     : z;
            v[pp][2] = vlo ? *(const float2*)(rowp + (size_t)wl * CIN + k + 8) : z;
            v[pp][3] = vhi ? *(const float2*)(rowp + (size_t)wh * CIN + k + 8) : z;
        }
        #pragma unroll
        for (int pp = 0; pp < 4; pp++) {
            const int p = wid * 8 + hf * 4 + pp;
            sts128(abase + p * 512 + lane * 16,
                   cvt2(v[pp][0].x, v[pp][0].y),   // a0: row g,   k lo
                   cvt2(v[pp][1].x, v[pp][1].y),   // a1: row g+8, k lo
                   cvt2(v[pp][2].x, v[pp][2].y),   // a2: row g,   k hi
                   cvt2(v[pp][3].x, v[pp][3].y));  // a3: row g+8, k hi
        }
    }
}

__device__ __forceinline__ void stageB(uint32_t bbase, int tap, int cc, int tid) {
    const uint4* src = g_w1b + (size_t)(tap * NCC + cc) * 1024;
    #pragma unroll
    for (int i = 0; i < 4; i++) {
        int idx = i * THREADS + tid;
        size_t ga = (size_t)__cvta_generic_to_global(src + idx);
        asm volatile("cp.async.cg.shared.global [%0], [%1], 16;"
                     :: "r"(bbase + idx * 16), "l"(ga) : "memory");
    }
}

__global__ void __launch_bounds__(THREADS, 1)
kp_mma_kernel(const float* __restrict__ x,
              const float* __restrict__ b1,
              const float* __restrict__ w2,
              const float* __restrict__ b2,
              float* __restrict__ out)
{
    extern __shared__ char smem[];
    const uint32_t sb = smem_u32(smem);
    const int tid  = threadIdx.x;
    const int wid  = tid >> 5;
    const int lane = tid & 31;
    const int wm   = wid >> 1;      // m-warp 0..3
    const int wn   = wid & 1;       // n-warp 0..1

    const int b  = blockIdx.x >> 4;
    const int rq = blockIdx.x & 15;

    float* b1s = reinterpret_cast<float*>(smem + OFF_B1S);
    float* w2s = reinterpret_cast<float*>(smem + OFF_W2S);
    if (tid < CHID) { b1s[tid] = b1[tid]; w2s[tid] = w2[tid]; }

    float acc[4][8][4];
    #pragma unroll
    for (int i = 0; i < 4; i++)
        #pragma unroll
        for (int nt = 0; nt < 8; nt++)
            #pragma unroll
            for (int c = 0; c < 4; c++) acc[i][nt][c] = 0.f;

    // prologue: stage chunk 0
    stageA(x, sb + OFF_A0, b, rq, 0, 0, wid, lane);
    stageB(sb + OFF_B0, 0, 0, tid);
    asm volatile("cp.async.commit_group;" ::: "memory");

    for (int ch = 0; ch < NCHUNK; ch++) {
        const int buf = ch & 1;
        if (ch < NCHUNK - 1) {
            const int nc = ch + 1, ncc = nc / NTAPS, ntap = nc % NTAPS;
            stageA(x, sb + ((nc & 1) ? OFF_A1 : OFF_A0), b, rq, ntap, ncc, wid, lane);
            stageB(sb + ((nc & 1) ? OFF_B1 : OFF_B0), ntap, ncc, tid);
            asm volatile("cp.async.commit_group;" ::: "memory");
            asm volatile("cp.async.wait_group 1;" ::: "memory");
        } else {
            asm volatile("cp.async.wait_group 0;" ::: "memory");
        }
        __syncthreads();

        const uint32_t Ab = sb + (buf ? OFF_A1 : OFF_A0);
        const uint32_t Bb = sb + (buf ? OFF_B1 : OFF_B0) + wn * 8192;
        #pragma unroll
        for (int ks = 0; ks < 4; ks++) {
            uint32_t af[4][4];
            #pragma unroll
            for (int i = 0; i < 4; i++)
                lds128(af[i], Ab + ((4 * wm + i) * 4 + ks) * 512 + lane * 16);
            #pragma unroll
            for (int j = 0; j < 4; j++) {
                uint32_t bf[4];
                lds128(bf, Bb + ks * 2048 + j * 512 + lane * 16);
                #pragma unroll
                for (int i = 0; i < 4; i++) {
                    mma_bf16(acc[i][2 * j],     af[i], bf[0], bf[1]);
                    mma_bf16(acc[i][2 * j + 1], af[i], bf[2], bf[3]);
                }
            }
        }
        __syncthreads();
    }

    // ---- fused epilogue: bias + ReLU + 1x1 conv + sigmoid ----
    float psum[8];
    #pragma unroll
    for (int i = 0; i < 4; i++)
        #pragma unroll
        for (int rh = 0; rh < 2; rh++) {
            float s = 0.f;
            #pragma unroll
            for (int nt = 0; nt < 8; nt++) {
                const int n0 = wn * 64 + nt * 8 + 2 * (lane & 3);
                s += fmaxf(acc[i][nt][rh * 2 + 0] + b1s[n0],     0.f) * w2s[n0];
                s += fmaxf(acc[i][nt][rh * 2 + 1] + b1s[n0 + 1], 0.f) * w2s[n0 + 1];
            }
            psum[i * 2 + rh] = s;
        }
    #pragma unroll
    for (int k = 0; k < 8; k++) {
        psum[k] += __shfl_xor_sync(0xffffffffu, psum[k], 1);
        psum[k] += __shfl_xor_sync(0xffffffffu, psum[k], 2);
    }
    float* part = reinterpret_cast<float*>(smem + OFF_A0);   // 512 floats, A0 idle now
    if ((lane & 3) == 0) {
        #pragma unroll
        for (int i = 0; i < 4; i++)
            #pragma unroll
            for (int rh = 0; rh < 2; rh++) {
                const int m = wm * 64 + i * 16 + (lane >> 2) + rh * 8;
                part[wn * 256 + m] = psum[i * 2 + rh];
            }
    }
    __syncthreads();
    {
        const float s = part[tid] + part[256 + tid] + b2[0];
        out[(size_t)blockIdx.x * 256 + tid] = 1.f / (1.f + __expf(-s));
    }
}

extern "C" void kernel_launch(void* const* d_in, const int* in_sizes, int n_in,
                              void* d_out, int out_size)
{
    const float* x  = (const float*)d_in[0];   // (32,64,64,384)
    const float* w1 = (const float*)d_in[1];   // (3,3,384,128) HWIO
    const float* b1 = (const float*)d_in[2];   // (128)
    const float* w2 = (const float*)d_in[3];   // (128)
    const float* b2 = (const float*)d_in[4];   // (1)
    float* out = (float*)d_out;                // (32,64,64,1)

    cudaFuncSetAttribute(kp_mma_kernel,
                         cudaFuncAttributeMaxDynamicSharedMemorySize, SMEM_TOTAL);

    prep_w1_kernel<<<216, 256>>>(w1);
    kp_mma_kernel<<<512, THREADS, SMEM_TOTAL>>>(x, b1, w2, b2, out);
}

// round 4
// speedup vs baseline: 5.8500x; 1.4678x over previous
#include <cuda_runtime.h>
#include <cuda_bf16.h>
#include <cstdint>

#define B_    32
#define CIN   384
#define CHID  128
#define NCC   6          // 384/64 channel chunks
#define NTAPS 9
#define NCHUNK (NCC * NTAPS)   // 54
#define THREADS 256

// As layout: word = k2*K2STRIDE + srow*RSTRIDE + (sc ^ ((k2&3)<<3))
#define RSTRIDE  96
#define K2STRIDE (6 * RSTRIDE)       // 576 words per k2 (== 0 mod 32 -> banks from sc only)

#define OFF_B1S 0
#define OFF_W2S 512
#define OFF_AS  1024
#define AS_BYTES (32 * K2STRIDE * 4)          // 73728
#define OFF_B0  (OFF_AS + AS_BYTES)           // 74752
#define OFF_B1  (OFF_B0 + 16384)              // 91136
#define SMEM_TOTAL (OFF_B1 + 16384)           // 107520

// W1 bf16 in mma-fragment order: [tap][cc][half][ks][j][lane] x 16B
__device__ __align__(16) uint4 g_w1b[NTAPS * NCC * 2 * 4 * 4 * 32];

__device__ __forceinline__ uint32_t smem_u32(const void* p) {
    uint32_t a;
    asm("{ .reg .u64 t; cvta.to.shared.u64 t, %1; cvt.u32.u64 %0, t; }" : "=r"(a) : "l"(p));
    return a;
}
__device__ __forceinline__ uint32_t cvt2(float lo, float hi) {
    __nv_bfloat162 h = __float22bfloat162_rn(make_float2(lo, hi));
    return *reinterpret_cast<uint32_t*>(&h);
}
__device__ __forceinline__ void sts32(uint32_t a, uint32_t v) {
    asm volatile("st.shared.b32 [%0], %1;" :: "r"(a), "r"(v) : "memory");
}
__device__ __forceinline__ void sts128(uint32_t a, uint32_t x, uint32_t y, uint32_t z, uint32_t w) {
    asm volatile("st.shared.v4.b32 [%0], {%1,%2,%3,%4};" :: "r"(a), "r"(x), "r"(y), "r"(z), "r"(w) : "memory");
}
__device__ __forceinline__ uint32_t lds32(uint32_t a) {
    uint32_t v;
    asm volatile("ld.shared.b32 %0, [%1];" : "=r"(v) : "r"(a));
    return v;
}
__device__ __forceinline__ void lds128(uint32_t* r, uint32_t a) {
    asm volatile("ld.shared.v4.b32 {%0,%1,%2,%3}, [%4];"
                 : "=r"(r[0]), "=r"(r[1]), "=r"(r[2]), "=r"(r[3]) : "r"(a));
}
__device__ __forceinline__ void mma_bf16(float* d, const uint32_t* a, uint32_t b0, uint32_t b1) {
    asm volatile("mma.sync.aligned.m16n8k16.row.col.f32.bf16.bf16.f32 "
                 "{%0,%1,%2,%3}, {%4,%5,%6,%7}, {%8,%9}, {%0,%1,%2,%3};"
                 : "+f"(d[0]), "+f"(d[1]), "+f"(d[2]), "+f"(d[3])
                 : "r"(a[0]), "r"(a[1]), "r"(a[2]), "r"(a[3]), "r"(b0), "r"(b1));
}

// ---- prep: W1 (HWIO fp32) -> g_w1b (bf16, mma-fragment order) ----
__global__ void prep_w1_kernel(const float* __restrict__ w1) {
    int u = blockIdx.x * 256 + threadIdx.x;          // 0..55295
    int lane = u & 31;  int r = u >> 5;
    int j    = r & 3;   r >>= 2;
    int ks   = r & 3;   r >>= 2;
    int half = r & 1;   r >>= 1;
    int cc   = r % NCC;
    int tap  = r / NCC;
    int g = lane >> 2, t = lane & 3;
    uint32_t wd[4];
    #pragma unroll
    for (int w = 0; w < 4; w++) {
        int nt = 2 * j + (w >> 1);
        int n  = half * 64 + nt * 8 + g;
        int kb = cc * 64 + ks * 16 + 2 * t + (w & 1) * 8;
        float f0 = w1[(size_t)(tap * CIN + kb) * CHID + n];
        float f1 = w1[(size_t)(tap * CIN + kb + 1) * CHID + n];
        wd[w] = cvt2(f0, f1);
    }
    g_w1b[u] = make_uint4(wd[0], wd[1], wd[2], wd[3]);
}

// ---- canonical A staging for one cc chunk: 6 halo rows x 64 cols x 64 ch ----
__device__ __forceinline__ void stageA_cc(const float* __restrict__ x, uint32_t abase,
                                          int b, int rq, int cc, int tid) {
    const int r0 = rq * 4 - 1;
    #pragma unroll
    for (int it = 0; it < 24; it++) {
        const int j    = it * THREADS + tid;      // 0..6143
        const int win  = j & 63;
        const int k2p  = (j >> 6) & 15;
        const int srow = j >> 10;                 // 0..5
        const int hin  = r0 + srow;
        if ((unsigned)hin < 64u) {
            const float4 f = *reinterpret_cast<const float4*>(
                x + ((size_t)((b * 64 + hin) * 64 + win)) * CIN + cc * 64 + k2p * 4);
            const int k2a = 2 * k2p, k2b = 2 * k2p + 1;
            const int sc  = win + 1;
            sts32(abase + (k2a * K2STRIDE + srow * RSTRIDE + (sc ^ ((k2a & 3) << 3))) * 4,
                  cvt2(f.x, f.y));
            sts32(abase + (k2b * K2STRIDE + srow * RSTRIDE + (sc ^ ((k2b & 3) << 3))) * 4,
                  cvt2(f.z, f.w));
        }
    }
}

__device__ __forceinline__ void stageB(uint32_t bbase, int tap, int cc, int tid) {
    const uint4* src = g_w1b + (size_t)(tap * NCC + cc) * 1024;
    #pragma unroll
    for (int i = 0; i < 4; i++) {
        int idx = i * THREADS + tid;
        size_t ga = (size_t)__cvta_generic_to_global(src + idx);
        asm volatile("cp.async.cg.shared.global [%0], [%1], 16;"
                     :: "r"(bbase + idx * 16), "l"(ga) : "memory");
    }
}

__global__ void __launch_bounds__(THREADS, 1)
kp_mma_kernel(const float* __restrict__ x,
              const float* __restrict__ b1,
              const float* __restrict__ w2,
              const float* __restrict__ b2,
              float* __restrict__ out)
{
    extern __shared__ char smem[];
    const uint32_t sb = smem_u32(smem);
    const int tid  = threadIdx.x;
    const int wid  = tid >> 5;
    const int lane = tid & 31;
    const int wm   = wid >> 1;      // m-warp 0..3 -> output row rq*4+wm
    const int wn   = wid & 1;       // n-warp 0..1
    const int g    = lane >> 2;
    const int t    = lane & 3;

    const int b  = blockIdx.x >> 4;
    const int rq = blockIdx.x & 15;

    float* b1s = reinterpret_cast<float*>(smem + OFF_B1S);
    float* w2s = reinterpret_cast<float*>(smem + OFF_W2S);
    if (tid < CHID) { b1s[tid] = b1[tid]; w2s[tid] = w2[tid]; }

    // zero As once: halo cells are never written afterwards -> stay 0
    {
        const uint32_t ab = sb + OFF_AS;
        #pragma unroll
        for (int i = 0; i < 18; i++)
            sts128(ab + (i * THREADS + tid) * 16, 0u, 0u, 0u, 0u);
    }

    // prologue: B chunk 0 in flight
    stageB(sb + OFF_B0, 0, 0, tid);
    asm volatile("cp.async.commit_group;" ::: "memory");
    __syncthreads();   // zeroed As visible before interior staging

    float acc[4][8][4];
    #pragma unroll
    for (int i = 0; i < 4; i++)
        #pragma unroll
        for (int nt = 0; nt < 8; nt++)
            #pragma unroll
            for (int c = 0; c < 4; c++) acc[i][nt][c] = 0.f;

    for (int cc = 0; cc < NCC; cc++) {
        stageA_cc(x, sb + OFF_AS, b, rq, cc, tid);
        __syncthreads();

        for (int tap = 0; tap < NTAPS; tap++) {
            const int ch  = cc * NTAPS + tap;
            const int buf = ch & 1;
            if (ch < NCHUNK - 1) {
                const int nc = ch + 1;
                stageB(sb + ((nc & 1) ? OFF_B1 : OFF_B0), nc % NTAPS, nc / NTAPS, tid);
                asm volatile("cp.async.commit_group;" ::: "memory");
                asm volatile("cp.async.wait_group 1;" ::: "memory");
            } else {
                asm volatile("cp.async.wait_group 0;" ::: "memory");
            }
            __syncthreads();

            const int dy = tap / 3 - 1, dx = tap % 3 - 1;
            const uint32_t Arow = sb + OFF_AS + (uint32_t)(wm + dy + 1) * (RSTRIDE * 4);
            const uint32_t Bb   = sb + (buf ? OFF_B1 : OFF_B0) + wn * 8192;
            const uint32_t sw   = (uint32_t)(t << 3);

            #pragma unroll
            for (int ks = 0; ks < 4; ks++) {
                const uint32_t k2lo = (uint32_t)(ks * 8 + t) * (K2STRIDE * 4);
                const uint32_t k2hi = k2lo + 4u * (K2STRIDE * 4);
                uint32_t af[4][4];
                #pragma unroll
                for (int i = 0; i < 4; i++) {
                    const uint32_t s0 = (uint32_t)((i * 16 + dx + 1 + g) ^ sw) * 4;
                    const uint32_t s1 = (uint32_t)((i * 16 + dx + 9 + g) ^ sw) * 4;
                    af[i][0] = lds32(Arow + k2lo + s0);
                    af[i][1] = lds32(Arow + k2lo + s1);
                    af[i][2] = lds32(Arow + k2hi + s0);
                    af[i][3] = lds32(Arow + k2hi + s1);
                }
                #pragma unroll
                for (int j = 0; j < 4; j++) {
                    uint32_t bf[4];
                    lds128(bf, Bb + ks * 2048 + j * 512 + lane * 16);
                    #pragma unroll
                    for (int i = 0; i < 4; i++) {
                        mma_bf16(acc[i][2 * j],     af[i], bf[0], bf[1]);
                        mma_bf16(acc[i][2 * j + 1], af[i], bf[2], bf[3]);
                    }
                }
            }
            __syncthreads();
        }
    }

    // ---- fused epilogue: bias + ReLU + 1x1 conv + sigmoid ----
    float psum[8];
    #pragma unroll
    for (int i = 0; i < 4; i++)
        #pragma unroll
        for (int rh = 0; rh < 2; rh++) {
            float s = 0.f;
            #pragma unroll
            for (int nt = 0; nt < 8; nt++) {
                const int n0 = wn * 64 + nt * 8 + 2 * t;
                s += fmaxf(acc[i][nt][rh * 2 + 0] + b1s[n0],     0.f) * w2s[n0];
                s += fmaxf(acc[i][nt][rh * 2 + 1] + b1s[n0 + 1], 0.f) * w2s[n0 + 1];
            }
            psum[i * 2 + rh] = s;
        }
    #pragma unroll
    for (int k = 0; k < 8; k++) {
        psum[k] += __shfl_xor_sync(0xffffffffu, psum[k], 1);
        psum[k] += __shfl_xor_sync(0xffffffffu, psum[k], 2);
    }
    float* part = reinterpret_cast<float*>(smem + OFF_AS);   // As idle now
    if (t == 0) {
        #pragma unroll
        for (int i = 0; i < 4; i++)
            #pragma unroll
            for (int rh = 0; rh < 2; rh++) {
                const int m = wm * 64 + i * 16 + g + rh * 8;
                part[wn * 256 + m] = psum[i * 2 + rh];
            }
    }
    __syncthreads();
    {
        const float s = part[tid] + part[256 + tid] + b2[0];
        out[(size_t)blockIdx.x * 256 + tid] = 1.f / (1.f + __expf(-s));
    }
}

extern "C" void kernel_launch(void* const* d_in, const int* in_sizes, int n_in,
                              void* d_out, int out_size)
{
    const float* x  = (const float*)d_in[0];   // (32,64,64,384)
    const float* w1 = (const float*)d_in[1];   // (3,3,384,128) HWIO
    const float* b1 = (const float*)d_in[2];   // (128)
    const float* w2 = (const float*)d_in[3];   // (128)
    const float* b2 = (const float*)d_in[4];   // (1)
    float* out = (float*)d_out;                // (32,64,64,1)

    cudaFuncSetAttribute(kp_mma_kernel,
                         cudaFuncAttributeMaxDynamicSharedMemorySize, SMEM_TOTAL);

    prep_w1_kernel<<<216, 256>>>(w1);
    kp_mma_kernel<<<512, THREADS, SMEM_TOTAL>>>(x, b1, w2, b2, out);
}

// round 5
// speedup vs baseline: 6.7553x; 1.1548x over previous
#include <cuda_runtime.h>
#include <cuda_bf16.h>
#include <cstdint>

#define B_    32
#define CIN   384
#define CHID  128
#define NCC   6
#define NTAPS 9
#define NCHUNK (NCC * NTAPS)   // 54
#define THREADS 512

// As layout: byte = srow*ROWB + col*128 + ((k8 ^ (col&7))<<4) + low8
#define ROWB     (66 * 128)               // 8448 bytes per halo row
#define AS_BYTES (6 * ROWB)               // 50688

#define OFF_B1S 0
#define OFF_W2S 512
#define OFF_AS  1024
#define OFF_B0  (OFF_AS + AS_BYTES)       // 51712
#define OFF_B1  (OFF_B0 + 16384)          // 68096
#define SMEM_TOTAL (OFF_B1 + 16384)       // 84480

// W1 bf16 in mma-fragment order: [tap][cc][half][ks][jj][lane] x 16B  (unchanged)
__device__ __align__(16) uint4 g_w1b[NTAPS * NCC * 2 * 4 * 4 * 32];

__device__ __forceinline__ uint32_t smem_u32(const void* p) {
    uint32_t a;
    asm("{ .reg .u64 t; cvta.to.shared.u64 t, %1; cvt.u32.u64 %0, t; }" : "=r"(a) : "l"(p));
    return a;
}
__device__ __forceinline__ uint32_t cvt2(float lo, float hi) {
    __nv_bfloat162 h = __float22bfloat162_rn(make_float2(lo, hi));
    return *reinterpret_cast<uint32_t*>(&h);
}
__device__ __forceinline__ void sts64(uint32_t a, uint32_t x, uint32_t y) {
    asm volatile("st.shared.v2.b32 [%0], {%1,%2};" :: "r"(a), "r"(x), "r"(y) : "memory");
}
__device__ __forceinline__ void sts128(uint32_t a, uint32_t x, uint32_t y, uint32_t z, uint32_t w) {
    asm volatile("st.shared.v4.b32 [%0], {%1,%2,%3,%4};" :: "r"(a), "r"(x), "r"(y), "r"(z), "r"(w) : "memory");
}
__device__ __forceinline__ void lds128(uint32_t* r, uint32_t a) {
    asm volatile("ld.shared.v4.b32 {%0,%1,%2,%3}, [%4];"
                 : "=r"(r[0]), "=r"(r[1]), "=r"(r[2]), "=r"(r[3]) : "r"(a));
}
__device__ __forceinline__ void ldmA(uint32_t* r, uint32_t a) {
    asm volatile("ldmatrix.sync.aligned.m8n8.x4.shared.b16 {%0,%1,%2,%3}, [%4];"
                 : "=r"(r[0]), "=r"(r[1]), "=r"(r[2]), "=r"(r[3]) : "r"(a));
}
__device__ __forceinline__ void mma_bf16(float* d, const uint32_t* a, uint32_t b0, uint32_t b1) {
    asm volatile("mma.sync.aligned.m16n8k16.row.col.f32.bf16.bf16.f32 "
                 "{%0,%1,%2,%3}, {%4,%5,%6,%7}, {%8,%9}, {%0,%1,%2,%3};"
                 : "+f"(d[0]), "+f"(d[1]), "+f"(d[2]), "+f"(d[3])
                 : "r"(a[0]), "r"(a[1]), "r"(a[2]), "r"(a[3]), "r"(b0), "r"(b1));
}

// ---- prep: W1 (HWIO fp32) -> g_w1b (bf16, mma-fragment order) ----
__global__ void prep_w1_kernel(const float* __restrict__ w1) {
    int u = blockIdx.x * 256 + threadIdx.x;          // 0..55295
    int lane = u & 31;  int r = u >> 5;
    int j    = r & 3;   r >>= 2;
    int ks   = r & 3;   r >>= 2;
    int half = r & 1;   r >>= 1;
    int cc   = r % NCC;
    int tap  = r / NCC;
    int g = lane >> 2, t = lane & 3;
    uint32_t wd[4];
    #pragma unroll
    for (int w = 0; w < 4; w++) {
        int nt = 2 * j + (w >> 1);
        int n  = half * 64 + nt * 8 + g;
        int kb = cc * 64 + ks * 16 + 2 * t + (w & 1) * 8;
        float f0 = w1[(size_t)(tap * CIN + kb) * CHID + n];
        float f1 = w1[(size_t)(tap * CIN + kb + 1) * CHID + n];
        wd[w] = cvt2(f0, f1);
    }
    g_w1b[u] = make_uint4(wd[0], wd[1], wd[2], wd[3]);
}

// ---- canonical A staging for one cc chunk: 6 halo rows x 64 cols x 64 ch ----
__device__ __forceinline__ void stageA_cc(const float* __restrict__ x, uint32_t abase,
                                          int b, int rq, int cc, int tid) {
    const int r0 = rq * 4 - 1;
    #pragma unroll
    for (int it = 0; it < 12; it++) {
        const int j    = it * THREADS + tid;      // 0..6143
        const int q    = j & 15;                  // float4 index (4 ch)
        const int win  = (j >> 4) & 63;
        const int srow = j >> 10;                 // 0..5
        const int hin  = r0 + srow;
        if ((unsigned)hin < 64u) {
            const float4 f = *reinterpret_cast<const float4*>(
                x + ((size_t)((b * 64 + hin) * 64 + win)) * CIN + cc * 64 + q * 4);
            const int sc = win + 1;
            const uint32_t addr = abase + srow * ROWB + sc * 128 +
                                  (((q >> 1) ^ (sc & 7)) << 4) + (q & 1) * 8;
            sts64(addr, cvt2(f.x, f.y), cvt2(f.z, f.w));
        }
    }
}

__device__ __forceinline__ void stageB(uint32_t bbase, int tap, int cc, int tid) {
    const uint4* src = g_w1b + (size_t)(tap * NCC + cc) * 1024;
    #pragma unroll
    for (int i = 0; i < 2; i++) {
        int idx = i * THREADS + tid;
        size_t ga = (size_t)__cvta_generic_to_global(src + idx);
        asm volatile("cp.async.cg.shared.global [%0], [%1], 16;"
                     :: "r"(bbase + idx * 16), "l"(ga) : "memory");
    }
}

__global__ void __launch_bounds__(THREADS, 1)
kp_mma_kernel(const float* __restrict__ x,
              const float* __restrict__ b1,
              const float* __restrict__ w2,
              const float* __restrict__ b2,
              float* __restrict__ out)
{
    extern __shared__ char smem[];
    const uint32_t sb = smem_u32(smem);
    const int tid  = threadIdx.x;
    const int wid  = tid >> 5;
    const int lane = tid & 31;
    const int wm   = wid >> 2;      // 0..3: output row rq*4+wm
    const int wn   = wid & 3;       // 0..3: n-slice of 32
    const int g    = lane >> 2;
    const int t    = lane & 3;
    const int l15  = lane & 15;
    const int kh   = lane >> 4;     // ldmatrix k-half

    const int b  = blockIdx.x >> 4;
    const int rq = blockIdx.x & 15;

    float* b1s = reinterpret_cast<float*>(smem + OFF_B1S);
    float* w2s = reinterpret_cast<float*>(smem + OFF_W2S);
    if (tid < CHID) { b1s[tid] = b1[tid]; w2s[tid] = w2[tid]; }

    // zero As once: halo cells are never written afterwards -> stay 0
    #pragma unroll
    for (int i = 0; i < 7; i++) {
        const int idx = i * THREADS + tid;
        if (idx < AS_BYTES / 16)
            sts128(sb + OFF_AS + idx * 16, 0u, 0u, 0u, 0u);
    }

    stageB(sb + OFF_B0, 0, 0, tid);
    asm volatile("cp.async.commit_group;" ::: "memory");
    __syncthreads();

    float acc[4][4][4];
    #pragma unroll
    for (int i = 0; i < 4; i++)
        #pragma unroll
        for (int nt = 0; nt < 4; nt++)
            #pragma unroll
            for (int c = 0; c < 4; c++) acc[i][nt][c] = 0.f;

    const uint32_t Bwn = (uint32_t)((wn >> 1) * 8192 + (wn & 1) * 1024);

    for (int cc = 0; cc < NCC; cc++) {
        stageA_cc(x, sb + OFF_AS, b, rq, cc, tid);
        __syncthreads();

        for (int tap = 0; tap < NTAPS; tap++) {
            const int ch  = cc * NTAPS + tap;
            const int buf = ch & 1;
            if (ch < NCHUNK - 1) {
                const int nc = ch + 1;
                stageB(sb + ((nc & 1) ? OFF_B1 : OFF_B0), nc % NTAPS, nc / NTAPS, tid);
                asm volatile("cp.async.commit_group;" ::: "memory");
                asm volatile("cp.async.wait_group 1;" ::: "memory");
            } else {
                asm volatile("cp.async.wait_group 0;" ::: "memory");
            }
            __syncthreads();

            const int dy = tap / 3 - 1, dx = tap % 3 - 1;
            const int c7 = (dx + 1 + l15) & 7;
            const uint32_t rowb = sb + OFF_AS + (uint32_t)(wm + dy + 1) * ROWB
                                + (uint32_t)(dx + 1 + l15) * 128;
            const uint32_t Bb = sb + (buf ? OFF_B1 : OFF_B0) + Bwn;

            #pragma unroll
            for (int ks = 0; ks < 4; ks++) {
                const uint32_t xo = (uint32_t)(((ks * 2 + kh) ^ c7) << 4);
                uint32_t af[4][4];
                #pragma unroll
                for (int i = 0; i < 4; i++)
                    ldmA(af[i], rowb + i * 2048 + xo);
                #pragma unroll
                for (int j = 0; j < 2; j++) {
                    uint32_t bf[4];
                    lds128(bf, Bb + ks * 2048 + j * 512 + lane * 16);
                    #pragma unroll
                    for (int i = 0; i < 4; i++) {
                        mma_bf16(acc[i][2 * j],     af[i], bf[0], bf[1]);
                        mma_bf16(acc[i][2 * j + 1], af[i], bf[2], bf[3]);
                    }
                }
            }
            __syncthreads();
        }
    }

    // ---- fused epilogue: bias + ReLU + 1x1 conv + sigmoid ----
    float psum[8];
    #pragma unroll
    for (int i = 0; i < 4; i++)
        #pragma unroll
        for (int rh = 0; rh < 2; rh++) {
            float s = 0.f;
            #pragma unroll
            for (int nt = 0; nt < 4; nt++) {
                const int n0 = wn * 32 + nt * 8 + 2 * t;
                s += fmaxf(acc[i][nt][rh * 2 + 0] + b1s[n0],     0.f) * w2s[n0];
                s += fmaxf(acc[i][nt][rh * 2 + 1] + b1s[n0 + 1], 0.f) * w2s[n0 + 1];
            }
            psum[i * 2 + rh] = s;
        }
    #pragma unroll
    for (int k = 0; k < 8; k++) {
        psum[k] += __shfl_xor_sync(0xffffffffu, psum[k], 1);
        psum[k] += __shfl_xor_sync(0xffffffffu, psum[k], 2);
    }
    float* part = reinterpret_cast<float*>(smem + OFF_AS);   // As idle now
    if (t == 0) {
        #pragma unroll
        for (int i = 0; i < 4; i++)
            #pragma unroll
            for (int rh = 0; rh < 2; rh++) {
                const int m = wm * 64 + i * 16 + g + rh * 8;
                part[wn * 256 + m] = psum[i * 2 + rh];
            }
    }
    __syncthreads();
    if (tid < 256) {
        const float s = part[tid] + part[256 + tid] + part[512 + tid] + part[768 + tid] + b2[0];
        out[(size_t)blockIdx.x * 256 + tid] = 1.f / (1.f + __expf(-s));
    }
}

extern "C" void kernel_launch(void* const* d_in, const int* in_sizes, int n_in,
                              void* d_out, int out_size)
{
    const float* x  = (const float*)d_in[0];   // (32,64,64,384)
    const float* w1 = (const float*)d_in[1];   // (3,3,384,128) HWIO
    const float* b1 = (const float*)d_in[2];   // (128)
    const float* w2 = (const float*)d_in[3];   // (128)
    const float* b2 = (const float*)d_in[4];   // (1)
    float* out = (float*)d_out;                // (32,64,64,1)

    cudaFuncSetAttribute(kp_mma_kernel,
                         cudaFuncAttributeMaxDynamicSharedMemorySize, SMEM_TOTAL);

    prep_w1_kernel<<<216, 256>>>(w1);
    kp_mma_kernel<<<512, THREADS, SMEM_TOTAL>>>(x, b1, w2, b2, out);
}

// round 6
// speedup vs baseline: 8.2268x; 1.2178x over previous
#include <cuda_runtime.h>
#include <cuda_bf16.h>
#include <cstdint>

#define B_    32
#define CIN   384
#define CHID  128
#define NCC   6
#define NTAPS 9
#define NCHUNK (NCC * NTAPS)   // 54
#define THREADS 256

// As layout: byte = srow*ROWB + col*128 + ((k8 ^ (col&7))<<4) + low8
#define ROWB     (66 * 128)               // 8448 bytes per halo row
#define AS_BYTES (4 * ROWB)               // 33792 (4 halo rows)

#define OFF_B1S 0
#define OFF_W2S 512
#define OFF_AS  1024
#define OFF_B   (OFF_AS + AS_BYTES)       // 34816; 3 buffers of 16384
#define SMEM_TOTAL (OFF_B + 3 * 16384)    // 83968

// W1 bf16 in mma-fragment order: [tap][cc][half][ks][jj][lane] x 16B
__device__ __align__(16) uint4 g_w1b[NTAPS * NCC * 2 * 4 * 4 * 32];

__device__ __forceinline__ uint32_t smem_u32(const void* p) {
    uint32_t a;
    asm("{ .reg .u64 t; cvta.to.shared.u64 t, %1; cvt.u32.u64 %0, t; }" : "=r"(a) : "l"(p));
    return a;
}
__device__ __forceinline__ uint32_t cvt2(float lo, float hi) {
    __nv_bfloat162 h = __float22bfloat162_rn(make_float2(lo, hi));
    return *reinterpret_cast<uint32_t*>(&h);
}
__device__ __forceinline__ void sts64(uint32_t a, uint32_t x, uint32_t y) {
    asm volatile("st.shared.v2.b32 [%0], {%1,%2};" :: "r"(a), "r"(x), "r"(y) : "memory");
}
__device__ __forceinline__ void sts128(uint32_t a, uint32_t x, uint32_t y, uint32_t z, uint32_t w) {
    asm volatile("st.shared.v4.b32 [%0], {%1,%2,%3,%4};" :: "r"(a), "r"(x), "r"(y), "r"(z), "r"(w) : "memory");
}
__device__ __forceinline__ void lds128(uint32_t* r, uint32_t a) {
    asm volatile("ld.shared.v4.b32 {%0,%1,%2,%3}, [%4];"
                 : "=r"(r[0]), "=r"(r[1]), "=r"(r[2]), "=r"(r[3]) : "r"(a));
}
__device__ __forceinline__ void ldmA(uint32_t* r, uint32_t a) {
    asm volatile("ldmatrix.sync.aligned.m8n8.x4.shared.b16 {%0,%1,%2,%3}, [%4];"
                 : "=r"(r[0]), "=r"(r[1]), "=r"(r[2]), "=r"(r[3]) : "r"(a));
}
__device__ __forceinline__ void mma_bf16(float* d, const uint32_t* a, uint32_t b0, uint32_t b1) {
    asm volatile("mma.sync.aligned.m16n8k16.row.col.f32.bf16.bf16.f32 "
                 "{%0,%1,%2,%3}, {%4,%5,%6,%7}, {%8,%9}, {%0,%1,%2,%3};"
                 : "+f"(d[0]), "+f"(d[1]), "+f"(d[2]), "+f"(d[3])
                 : "r"(a[0]), "r"(a[1]), "r"(a[2]), "r"(a[3]), "r"(b0), "r"(b1));
}

// ---- prep: W1 (HWIO fp32) -> g_w1b (bf16, mma-fragment order) ----
__global__ void prep_w1_kernel(const float* __restrict__ w1) {
    int u = blockIdx.x * 256 + threadIdx.x;          // 0..55295
    int lane = u & 31;  int r = u >> 5;
    int j    = r & 3;   r >>= 2;
    int ks   = r & 3;   r >>= 2;
    int half = r & 1;   r >>= 1;
    int cc   = r % NCC;
    int tap  = r / NCC;
    int g = lane >> 2, t = lane & 3;
    uint32_t wd[4];
    #pragma unroll
    for (int w = 0; w < 4; w++) {
        int nt = 2 * j + (w >> 1);
        int n  = half * 64 + nt * 8 + g;
        int kb = cc * 64 + ks * 16 + 2 * t + (w & 1) * 8;
        float f0 = w1[(size_t)(tap * CIN + kb) * CHID + n];
        float f1 = w1[(size_t)(tap * CIN + kb + 1) * CHID + n];
        wd[w] = cvt2(f0, f1);
    }
    g_w1b[u] = make_uint4(wd[0], wd[1], wd[2], wd[3]);
}

// ---- canonical A staging for one cc chunk: 4 halo rows x 64 cols x 64 ch ----
__device__ __forceinline__ void stageA_cc(const float* __restrict__ x, uint32_t abase,
                                          int b, int rp, int cc, int tid) {
    const int r0 = rp * 2 - 1;
    #pragma unroll
    for (int it = 0; it < 16; it++) {
        const int j    = it * THREADS + tid;      // 0..4095
        const int q    = j & 15;                  // float4 index (4 ch)
        const int win  = (j >> 4) & 63;
        const int srow = j >> 10;                 // 0..3
        const int hin  = r0 + srow;
        if ((unsigned)hin < 64u) {
            const float4 f = *reinterpret_cast<const float4*>(
                x + ((size_t)((b * 64 + hin) * 64 + win)) * CIN + cc * 64 + q * 4);
            const int sc = win + 1;
            const uint32_t addr = abase + srow * ROWB + sc * 128 +
                                  (((q >> 1) ^ (sc & 7)) << 4) + (q & 1) * 8;
            sts64(addr, cvt2(f.x, f.y), cvt2(f.z, f.w));
        }
    }
}

__device__ __forceinline__ void stageB(uint32_t bbase, int chunk, int tid) {
    const uint4* src = g_w1b + (size_t)((chunk % NTAPS) * NCC + (chunk / NTAPS)) * 1024;
    #pragma unroll
    for (int i = 0; i < 4; i++) {
        int idx = i * THREADS + tid;
        size_t ga = (size_t)__cvta_generic_to_global(src + idx);
        asm volatile("cp.async.cg.shared.global [%0], [%1], 16;"
                     :: "r"(bbase + idx * 16), "l"(ga) : "memory");
    }
}

__global__ void __launch_bounds__(THREADS, 2)
kp_mma_kernel(const float* __restrict__ x,
              const float* __restrict__ b1,
              const float* __restrict__ w2,
              const float* __restrict__ b2,
              float* __restrict__ out)
{
    extern __shared__ char smem[];
    const uint32_t sb = smem_u32(smem);
    const int tid  = threadIdx.x;
    const int wid  = tid >> 5;
    const int lane = tid & 31;
    const int wm   = wid >> 2;      // 0..1: output row rp*2+wm
    const int wn   = wid & 3;       // 0..3: n-slice of 32
    const int g    = lane >> 2;
    const int t    = lane & 3;
    const int l15  = lane & 15;
    const int kh   = lane >> 4;     // ldmatrix k-half

    const int b  = blockIdx.x >> 5;
    const int rp = blockIdx.x & 31;

    float* b1s = reinterpret_cast<float*>(smem + OFF_B1S);
    float* w2s = reinterpret_cast<float*>(smem + OFF_W2S);
    if (tid < CHID) { b1s[tid] = b1[tid]; w2s[tid] = w2[tid]; }

    // zero As once: halo cells are never written afterwards -> stay 0
    #pragma unroll
    for (int i = 0; i < 9; i++) {
        const int idx = i * THREADS + tid;
        if (idx < AS_BYTES / 16)
            sts128(sb + OFF_AS + idx * 16, 0u, 0u, 0u, 0u);
    }

    // prologue: B chunks 0 and 1 in flight (separate groups)
    stageB(sb + OFF_B, 0, tid);
    asm volatile("cp.async.commit_group;" ::: "memory");
    stageB(sb + OFF_B + 16384, 1, tid);
    asm volatile("cp.async.commit_group;" ::: "memory");

    float acc[2][4][4][4];
    #pragma unroll
    for (int i2 = 0; i2 < 2; i2++)
        #pragma unroll
        for (int i = 0; i < 4; i++)
            #pragma unroll
            for (int nt = 0; nt < 4; nt++)
                #pragma unroll
                for (int c = 0; c < 4; c++) acc[i2][i][nt][c] = 0.f;
    float (*accw)[4][4] = acc[0];   // flatten: wm fixed per warp -> use acc[0..1] as 2x regs? no
    (void)accw;

    const uint32_t Bwn = (uint32_t)((wn >> 1) * 8192 + (wn & 1) * 1024);

    for (int ch = 0; ch < NCHUNK; ch++) {
        const int tap = ch % NTAPS;
        // wait for buffer ch, then one block barrier
        if (ch < NCHUNK - 1) asm volatile("cp.async.wait_group 1;" ::: "memory");
        else                 asm volatile("cp.async.wait_group 0;" ::: "memory");
        __syncthreads();
        if (tap == 0) {                 // new cc: restage A (prev readers passed barrier)
            stageA_cc(x, sb + OFF_AS, b, rp, ch / NTAPS, tid);
            __syncthreads();
        }
        if (ch + 2 < NCHUNK) {          // stage ch+2 into buffer consumed at ch-1
            stageB(sb + OFF_B + ((ch + 2) % 3) * 16384, ch + 2, tid);
            asm volatile("cp.async.commit_group;" ::: "memory");
        }

        const int dy = tap / 3 - 1, dx = tap % 3 - 1;
        const int c7 = (dx + 1 + l15) & 7;
        const uint32_t rowb = sb + OFF_AS + (uint32_t)(wm + dy + 1) * ROWB
                            + (uint32_t)(dx + 1 + l15) * 128;
        const uint32_t Bb = sb + OFF_B + (uint32_t)(ch % 3) * 16384 + Bwn;

        #pragma unroll
        for (int ks = 0; ks < 4; ks++) {
            const uint32_t xo = (uint32_t)(((ks * 2 + kh) ^ c7) << 4);
            uint32_t af[4][4];
            #pragma unroll
            for (int i = 0; i < 4; i++)
                ldmA(af[i], rowb + i * 2048 + xo);
            #pragma unroll
            for (int j = 0; j < 2; j++) {
                uint32_t bf[4];
                lds128(bf, Bb + ks * 2048 + j * 512 + lane * 16);
                #pragma unroll
                for (int i = 0; i < 4; i++) {
                    mma_bf16(acc[0][i][2 * j],     af[i], bf[0], bf[1]);
                    mma_bf16(acc[0][i][2 * j + 1], af[i], bf[2], bf[3]);
                }
            }
        }
    }

    // ---- fused epilogue: bias + ReLU + 1x1 conv + sigmoid ----
    float psum[8];
    #pragma unroll
    for (int i = 0; i < 4; i++)
        #pragma unroll
        for (int rh = 0; rh < 2; rh++) {
            float s = 0.f;
            #pragma unroll
            for (int nt = 0; nt < 4; nt++) {
                const int n0 = wn * 32 + nt * 8 + 2 * t;
                s += fmaxf(acc[0][i][nt][rh * 2 + 0] + b1s[n0],     0.f) * w2s[n0];
                s += fmaxf(acc[0][i][nt][rh * 2 + 1] + b1s[n0 + 1], 0.f) * w2s[n0 + 1];
            }
            psum[i * 2 + rh] = s;
        }
    #pragma unroll
    for (int k = 0; k < 8; k++) {
        psum[k] += __shfl_xor_sync(0xffffffffu, psum[k], 1);
        psum[k] += __shfl_xor_sync(0xffffffffu, psum[k], 2);
    }
    __syncthreads();                                   // all A-reads done before reuse
    float* part = reinterpret_cast<float*>(smem + OFF_AS);
    if (t == 0) {
        #pragma unroll
        for (int i = 0; i < 4; i++)
            #pragma unroll
            for (int rh = 0; rh < 2; rh++) {
                const int m = wm * 64 + i * 16 + g + rh * 8;   // 0..127
                part[wn * 128 + m] = psum[i * 2 + rh];
            }
    }
    __syncthreads();
    if (tid < 128) {
        const float s = part[tid] + part[128 + tid] + part[256 + tid] + part[384 + tid] + b2[0];
        out[(size_t)blockIdx.x * 128 + tid] = 1.f / (1.f + __expf(-s));
    }
}

extern "C" void kernel_launch(void* const* d_in, const int* in_sizes, int n_in,
                              void* d_out, int out_size)
{
    const float* x  = (const float*)d_in[0];   // (32,64,64,384)
    const float* w1 = (const float*)d_in[1];   // (3,3,384,128) HWIO
    const float* b1 = (const float*)d_in[2];   // (128)
    const float* w2 = (const float*)d_in[3];   // (128)
    const float* b2 = (const float*)d_in[4];   // (1)
    float* out = (float*)d_out;                // (32,64,64,1)

    cudaFuncSetAttribute(kp_mma_kernel,
                         cudaFuncAttributeMaxDynamicSharedMemorySize, SMEM_TOTAL);

    prep_w1_kernel<<<216, 256>>>(w1);
    kp_mma_kernel<<<1024, THREADS, SMEM_TOTAL>>>(x, b1, w2, b2, out);
}

// round 7
// speedup vs baseline: 8.5418x; 1.0383x over previous
#include <cuda_runtime.h>
#include <cuda_bf16.h>
#include <cstdint>

#define B_    32
#define CIN   384
#define CHID  128
#define NCC   6
#define NTAPS 9
#define NCHUNK (NCC * NTAPS)   // 54
#define THREADS 256

// As layout: byte = srow*ROWB + col*128 + ((k8 ^ (col&7))<<4) + low8
#define ROWB     (66 * 128)               // 8448 bytes per halo row
#define AS_BYTES (4 * ROWB)               // 33792 (4 halo rows)

#define OFF_B1S 0
#define OFF_W2S 512
#define OFF_AS  1024
#define OFF_B   (OFF_AS + AS_BYTES)       // 34816; 4 buffers of 16384
#define SMEM_TOTAL (OFF_B + 4 * 16384)    // 100352

// W1 bf16 in mma-fragment order: [tap][cc][half][ks][jj][lane] x 16B
__device__ __align__(16) uint4 g_w1b[NTAPS * NCC * 2 * 4 * 4 * 32];

__device__ __forceinline__ uint32_t smem_u32(const void* p) {
    uint32_t a;
    asm("{ .reg .u64 t; cvta.to.shared.u64 t, %1; cvt.u32.u64 %0, t; }" : "=r"(a) : "l"(p));
    return a;
}
__device__ __forceinline__ uint32_t cvt2(float lo, float hi) {
    __nv_bfloat162 h = __float22bfloat162_rn(make_float2(lo, hi));
    return *reinterpret_cast<uint32_t*>(&h);
}
__device__ __forceinline__ void sts64(uint32_t a, uint32_t x, uint32_t y) {
    asm volatile("st.shared.v2.b32 [%0], {%1,%2};" :: "r"(a), "r"(x), "r"(y) : "memory");
}
__device__ __forceinline__ void sts128(uint32_t a, uint32_t x, uint32_t y, uint32_t z, uint32_t w) {
    asm volatile("st.shared.v4.b32 [%0], {%1,%2,%3,%4};" :: "r"(a), "r"(x), "r"(y), "r"(z), "r"(w) : "memory");
}
__device__ __forceinline__ void lds128(uint32_t* r, uint32_t a) {
    asm volatile("ld.shared.v4.b32 {%0,%1,%2,%3}, [%4];"
                 : "=r"(r[0]), "=r"(r[1]), "=r"(r[2]), "=r"(r[3]) : "r"(a));
}
__device__ __forceinline__ void ldmA(uint32_t* r, uint32_t a) {
    asm volatile("ldmatrix.sync.aligned.m8n8.x4.shared.b16 {%0,%1,%2,%3}, [%4];"
                 : "=r"(r[0]), "=r"(r[1]), "=r"(r[2]), "=r"(r[3]) : "r"(a));
}
__device__ __forceinline__ void mma_bf16(float* d, const uint32_t* a, uint32_t b0, uint32_t b1) {
    asm volatile("mma.sync.aligned.m16n8k16.row.col.f32.bf16.bf16.f32 "
                 "{%0,%1,%2,%3}, {%4,%5,%6,%7}, {%8,%9}, {%0,%1,%2,%3};"
                 : "+f"(d[0]), "+f"(d[1]), "+f"(d[2]), "+f"(d[3])
                 : "r"(a[0]), "r"(a[1]), "r"(a[2]), "r"(a[3]), "r"(b0), "r"(b1));
}

// ---- prep: W1 (HWIO fp32) -> g_w1b (bf16, mma-fragment order) ----
__global__ void prep_w1_kernel(const float* __restrict__ w1) {
    int u = blockIdx.x * 256 + threadIdx.x;          // 0..55295
    int lane = u & 31;  int r = u >> 5;
    int j    = r & 3;   r >>= 2;
    int ks   = r & 3;   r >>= 2;
    int half = r & 1;   r >>= 1;
    int cc   = r % NCC;
    int tap  = r / NCC;
    int g = lane >> 2, t = lane & 3;
    uint32_t wd[4];
    #pragma unroll
    for (int w = 0; w < 4; w++) {
        int nt = 2 * j + (w >> 1);
        int n  = half * 64 + nt * 8 + g;
        int kb = cc * 64 + ks * 16 + 2 * t + (w & 1) * 8;
        float f0 = w1[(size_t)(tap * CIN + kb) * CHID + n];
        float f1 = w1[(size_t)(tap * CIN + kb + 1) * CHID + n];
        wd[w] = cvt2(f0, f1);
    }
    g_w1b[u] = make_uint4(wd[0], wd[1], wd[2], wd[3]);
}

// ---- canonical A staging for one cc chunk: 4 halo rows x 64 cols x 64 ch ----
__device__ __forceinline__ void stageA_cc(const float* __restrict__ x, uint32_t abase,
                                          int b, int rp, int cc, int tid) {
    const int r0 = rp * 2 - 1;
    #pragma unroll
    for (int it = 0; it < 16; it++) {
        const int j    = it * THREADS + tid;      // 0..4095
        const int q    = j & 15;                  // float4 index (4 ch)
        const int win  = (j >> 4) & 63;
        const int srow = j >> 10;                 // 0..3
        const int hin  = r0 + srow;
        if ((unsigned)hin < 64u) {
            const float4 f = *reinterpret_cast<const float4*>(
                x + ((size_t)((b * 64 + hin) * 64 + win)) * CIN + cc * 64 + q * 4);
            const int sc = win + 1;
            const uint32_t addr = abase + srow * ROWB + sc * 128 +
                                  (((q >> 1) ^ (sc & 7)) << 4) + (q & 1) * 8;
            sts64(addr, cvt2(f.x, f.y), cvt2(f.z, f.w));
        }
    }
}

__device__ __forceinline__ void stageB(uint32_t bbase, int chunk, int tid) {
    const uint4* src = g_w1b + (size_t)((chunk % NTAPS) * NCC + (chunk / NTAPS)) * 1024;
    #pragma unroll
    for (int i = 0; i < 4; i++) {
        int idx = i * THREADS + tid;
        size_t ga = (size_t)__cvta_generic_to_global(src + idx);
        asm volatile("cp.async.cg.shared.global [%0], [%1], 16;"
                     :: "r"(bbase + idx * 16), "l"(ga) : "memory");
    }
}

__global__ void __launch_bounds__(THREADS, 2)
kp_mma_kernel(const float* __restrict__ x,
              const float* __restrict__ b1,
              const float* __restrict__ w2,
              const float* __restrict__ b2,
              float* __restrict__ out)
{
    extern __shared__ char smem[];
    const uint32_t sb = smem_u32(smem);
    const int tid  = threadIdx.x;
    const int wid  = tid >> 5;
    const int lane = tid & 31;
    const int wm   = wid >> 2;      // 0..1: output row rp*2+wm
    const int wn   = wid & 3;       // 0..3: n-slice of 32
    const int g    = lane >> 2;
    const int t    = lane & 3;
    const int l15  = lane & 15;
    const int kh   = lane >> 4;     // ldmatrix k-half

    const int b  = blockIdx.x >> 5;
    const int rp = blockIdx.x & 31;

    float* b1s = reinterpret_cast<float*>(smem + OFF_B1S);
    float* w2s = reinterpret_cast<float*>(smem + OFF_W2S);
    if (tid < CHID) { b1s[tid] = b1[tid]; w2s[tid] = w2[tid]; }

    // zero As once: halo cells are never written afterwards -> stay 0
    #pragma unroll
    for (int i = 0; i < 9; i++) {
        const int idx = i * THREADS + tid;
        if (idx < AS_BYTES / 16)
            sts128(sb + OFF_AS + idx * 16, 0u, 0u, 0u, 0u);
    }

    // prologue: B chunks 0,1 as one group
    stageB(sb + OFF_B + (0 % 4) * 16384, 0, tid);
    stageB(sb + OFF_B + (1 % 4) * 16384, 1, tid);
    asm volatile("cp.async.commit_group;" ::: "memory");

    float acc[4][4][4];
    #pragma unroll
    for (int i = 0; i < 4; i++)
        #pragma unroll
        for (int nt = 0; nt < 4; nt++)
            #pragma unroll
            for (int c = 0; c < 4; c++) acc[i][nt][c] = 0.f;

    const uint32_t Bwn = (uint32_t)((wn >> 1) * 8192 + (wn & 1) * 1024);

    for (int cc = 0; cc < NCC; cc++) {
        // ---- A restage block (group straddle never crosses this) ----
        asm volatile("cp.async.wait_group 0;" ::: "memory");
        __syncthreads();
        stageA_cc(x, sb + OFF_AS, b, rp, cc, tid);
        __syncthreads();

        // ---- 5 groups per cc: taps {0,1},{2,3},{4,5},{6,7},{8} ----
        #pragma unroll
        for (int grp = 0; grp < 5; grp++) {
            const int t0   = grp * 2;               // 0,2,4,6,8
            const int gsz  = (grp == 4) ? 1 : 2;
            const int ch0  = cc * NTAPS + t0;

            if (grp > 0) {
                asm volatile("cp.async.wait_group 0;" ::: "memory");
                __syncthreads();
            }
            // stage next group's B chunks (1-deep lookahead, disjoint buffers mod 4)
            {
                const int ns = ch0 + gsz;           // next group's first chunk
                if (ns < NCHUNK) {
                    const int ncnt = (t0 == 6) ? 1 : 2;   // next group size
                    stageB(sb + OFF_B + (uint32_t)(ns % 4) * 16384, ns, tid);
                    if (ncnt == 2 && ns + 1 < NCHUNK)
                        stageB(sb + OFF_B + (uint32_t)((ns + 1) % 4) * 16384, ns + 1, tid);
                    asm volatile("cp.async.commit_group;" ::: "memory");
                }
            }

            #pragma unroll
            for (int u = 0; u < 2; u++) {
                if (u >= gsz) break;
                const int tap = t0 + u;
                const int ch  = ch0 + u;
                const int dy = tap / 3 - 1, dx = tap % 3 - 1;
                const int c7 = (dx + 1 + l15) & 7;
                const uint32_t rowb = sb + OFF_AS + (uint32_t)(wm + dy + 1) * ROWB
                                    + (uint32_t)(dx + 1 + l15) * 128;
                const uint32_t Bb = sb + OFF_B + (uint32_t)(ch % 4) * 16384 + Bwn;

                #pragma unroll
                for (int ks = 0; ks < 4; ks++) {
                    const uint32_t xo = (uint32_t)(((ks * 2 + kh) ^ c7) << 4);
                    uint32_t af[4][4];
                    #pragma unroll
                    for (int i = 0; i < 4; i++)
                        ldmA(af[i], rowb + i * 2048 + xo);
                    #pragma unroll
                    for (int j = 0; j < 2; j++) {
                        uint32_t bf[4];
                        lds128(bf, Bb + ks * 2048 + j * 512 + lane * 16);
                        #pragma unroll
                        for (int i = 0; i < 4; i++) {
                            mma_bf16(acc[i][2 * j],     af[i], bf[0], bf[1]);
                            mma_bf16(acc[i][2 * j + 1], af[i], bf[2], bf[3]);
                        }
                    }
                }
            }
        }
    }

    // ---- fused epilogue: bias + ReLU + 1x1 conv + sigmoid ----
    float psum[8];
    #pragma unroll
    for (int i = 0; i < 4; i++)
        #pragma unroll
        for (int rh = 0; rh < 2; rh++) {
            float s = 0.f;
            #pragma unroll
            for (int nt = 0; nt < 4; nt++) {
                const int n0 = wn * 32 + nt * 8 + 2 * t;
                s += fmaxf(acc[i][nt][rh * 2 + 0] + b1s[n0],     0.f) * w2s[n0];
                s += fmaxf(acc[i][nt][rh * 2 + 1] + b1s[n0 + 1], 0.f) * w2s[n0 + 1];
            }
            psum[i * 2 + rh] = s;
        }
    #pragma unroll
    for (int k = 0; k < 8; k++) {
        psum[k] += __shfl_xor_sync(0xffffffffu, psum[k], 1);
        psum[k] += __shfl_xor_sync(0xffffffffu, psum[k], 2);
    }
    __syncthreads();                                   // all A-reads done before reuse
    float* part = reinterpret_cast<float*>(smem + OFF_AS);
    if (t == 0) {
        #pragma unroll
        for (int i = 0; i < 4; i++)
            #pragma unroll
            for (int rh = 0; rh < 2; rh++) {
                const int m = wm * 64 + i * 16 + g + rh * 8;   // 0..127
                part[wn * 128 + m] = psum[i * 2 + rh];
            }
    }
    __syncthreads();
    if (tid < 128) {
        const float s = part[tid] + part[128 + tid] + part[256 + tid] + part[384 + tid] + b2[0];
        out[(size_t)blockIdx.x * 128 + tid] = 1.f / (1.f + __expf(-s));
    }
}

extern "C" void kernel_launch(void* const* d_in, const int* in_sizes, int n_in,
                              void* d_out, int out_size)
{
    const float* x  = (const float*)d_in[0];   // (32,64,64,384)
    const float* w1 = (const float*)d_in[1];   // (3,3,384,128) HWIO
    const float* b1 = (const float*)d_in[2];   // (128)
    const float* w2 = (const float*)d_in[3];   // (128)
    const float* b2 = (const float*)d_in[4];   // (1)
    float* out = (float*)d_out;                // (32,64,64,1)

    cudaFuncSetAttribute(kp_mma_kernel,
                         cudaFuncAttributeMaxDynamicSharedMemorySize, SMEM_TOTAL);

    prep_w1_kernel<<<216, 256>>>(w1);
    kp_mma_kernel<<<1024, THREADS, SMEM_TOTAL>>>(x, b1, w2, b2, out);
}